// round 3
// baseline (speedup 1.0000x reference)
#include <cuda_runtime.h>

#define NPRED 8400
#define NCLS  80
#define NSORT 16384
#define NMSN  1024
#define MAXDET 300
#define SORT_THREADS 1024

// ---------------- scratch (device globals; no allocation allowed) ----------
__device__ float              g_conf[NPRED];
__device__ int                g_cls[NPRED];
__device__ float              g_box[NPRED * 4];
__device__ unsigned long long g_key[NSORT];

__device__ float g_topconf[NMSN];
__device__ float g_ob[NMSN * 4];    // class-offset boxes (for IoU)
__device__ float g_area[NMSN];
__device__ float g_outb[NMSN * 4];  // original boxes (for output)
__device__ float g_cf[NMSN];        // class as float
__device__ int   g_keep0[NMSN];
__device__ unsigned long long g_mask[NMSN * 16];
__device__ int   g_keepf[NMSN];

// ---------------- kernel 1: conf/argmax/boxes/sort-keys (batch 0 only) -----
__global__ void k_prep(const float* __restrict__ p) {
    int a = blockIdx.x * blockDim.x + threadIdx.x;
    if (a >= NSORT) return;
    if (a < NPRED) {
        float cx = p[0 * NPRED + a];
        float cy = p[1 * NPRED + a];
        float w  = p[2 * NPRED + a];
        float h  = p[3 * NPRED + a];
        float hw = __fmul_rn(w, 0.5f);
        float hh = __fmul_rn(h, 0.5f);
        g_box[a * 4 + 0] = __fsub_rn(cx, hw);
        g_box[a * 4 + 1] = __fsub_rn(cy, hh);
        g_box[a * 4 + 2] = __fadd_rn(cx, hw);
        g_box[a * 4 + 3] = __fadd_rn(cy, hh);

        float m = p[4 * NPRED + a];
        int cl = 0;
        #pragma unroll 4
        for (int c = 1; c < NCLS; ++c) {
            float v = p[(4 + c) * NPRED + a];
            if (v > m) { m = v; cl = c; }   // first-max tie-break (strict >)
        }
        g_conf[a] = m;
        g_cls[a]  = cl;

        float mc = (m > 0.25f) ? m : -1.0f;
        unsigned u = __float_as_uint(mc);
        u = (u & 0x80000000u) ? ~u : (u | 0x80000000u);  // monotone asc map
        unsigned k = ~u;                                  // descending conf
        g_key[a] = ((unsigned long long)k << 32) | (unsigned)a;
    } else {
        g_key[a] = 0xFFFFFFFFFFFFFFFFull;  // sentinel: sorts last
    }
}

// ---------------- kernel 2: bitonic sort (asc) + top-1024 gather -----------
__global__ void k_sort() {
    extern __shared__ unsigned long long sk[];
    int t = threadIdx.x;
    for (int i = t; i < NSORT; i += SORT_THREADS) sk[i] = g_key[i];
    __syncthreads();

    for (int size = 2; size <= NSORT; size <<= 1) {
        for (int stride = size >> 1; stride > 0; stride >>= 1) {
            for (int b = t; b < NSORT / 2; b += SORT_THREADS) {
                int low = b & (stride - 1);
                int i = ((b ^ low) << 1) | low;
                int j = i + stride;
                unsigned long long A = sk[i], B = sk[j];
                bool asc = ((i & size) == 0);
                if ((A > B) == asc) { sk[i] = B; sk[j] = A; }
            }
            __syncthreads();
        }
    }

    if (t < NMSN) {
        unsigned long long key = sk[t];
        int idx = (int)(key & 0xFFFFFFFFu);
        float tc = -1.0f, b0 = 0.f, b1 = 0.f, b2 = 0.f, b3 = 0.f, cf = 0.f;
        if (idx >= 0 && idx < NPRED) {
            float c = g_conf[idx];
            tc = (c > 0.25f) ? c : -1.0f;
            b0 = g_box[idx * 4 + 0];
            b1 = g_box[idx * 4 + 1];
            b2 = g_box[idx * 4 + 2];
            b3 = g_box[idx * 4 + 3];
            cf = (float)g_cls[idx];
        }
        g_topconf[t] = tc;
        g_keep0[t]   = (tc > 0.25f) ? 1 : 0;
        g_outb[t * 4 + 0] = b0;
        g_outb[t * 4 + 1] = b1;
        g_outb[t * 4 + 2] = b2;
        g_outb[t * 4 + 3] = b3;
        g_cf[t] = cf;

        float off = __fmul_rn(cf, 7680.0f);
        float o0 = __fadd_rn(b0, off);
        float o1 = __fadd_rn(b1, off);
        float o2 = __fadd_rn(b2, off);
        float o3 = __fadd_rn(b3, off);
        g_ob[t * 4 + 0] = o0;
        g_ob[t * 4 + 1] = o1;
        g_ob[t * 4 + 2] = o2;
        g_ob[t * 4 + 3] = o3;
        // area on OFFSET boxes (matches reference's quantized arithmetic)
        g_area[t] = __fmul_rn(__fsub_rn(o2, o0), __fsub_rn(o3, o1));
    }
}

// ---------------- kernel 3: 1024x1024 IoU suppression bitmask --------------
__global__ void k_mask() {
    __shared__ float sx1[64], sy1[64], sx2[64], sy2[64], sa[64];
    int t = threadIdx.x;                 // 0..63
    int col0 = blockIdx.x * 64;
    int r = blockIdx.y * 64 + t;
    int j = col0 + t;
    sx1[t] = g_ob[j * 4 + 0];
    sy1[t] = g_ob[j * 4 + 1];
    sx2[t] = g_ob[j * 4 + 2];
    sy2[t] = g_ob[j * 4 + 3];
    sa[t]  = g_area[j];
    __syncthreads();

    float x1 = g_ob[r * 4 + 0];
    float y1 = g_ob[r * 4 + 1];
    float x2 = g_ob[r * 4 + 2];
    float y2 = g_ob[r * 4 + 3];
    float ar = g_area[r];

    unsigned long long bits = 0ull;
    #pragma unroll 8
    for (int jj = 0; jj < 64; ++jj) {
        int cidx = col0 + jj;
        if (cidx <= r) continue;
        float lx = fmaxf(x1, sx1[jj]);
        float ly = fmaxf(y1, sy1[jj]);
        float rx = fminf(x2, sx2[jj]);
        float ry = fminf(y2, sy2[jj]);
        float ww = fmaxf(__fsub_rn(rx, lx), 0.0f);
        float hh = fmaxf(__fsub_rn(ry, ly), 0.0f);
        float inter = __fmul_rn(ww, hh);
        float den = __fadd_rn(__fsub_rn(__fadd_rn(ar, sa[jj]), inter), 1e-7f);
        float iou = __fdiv_rn(inter, den);
        if (iou > 0.45f) bits |= (1ull << jj);
    }
    g_mask[r * 16 + blockIdx.x] = bits;
}

// ---------------- kernel 4: greedy serial NMS pass (one warp) --------------
__global__ void k_serial() {
    int lane = threadIdx.x;  // 32 threads
    unsigned long long remv = 0ull;
    unsigned long long m = (lane < 16) ? g_mask[lane] : 0ull;
    for (int i = 0; i < NMSN; ++i) {
        unsigned long long nxt = 0ull;
        if (i + 1 < NMSN && lane < 16) nxt = g_mask[(i + 1) * 16 + lane];
        int k0 = g_keep0[i];
        unsigned long long sup = __shfl_sync(0xffffffffu, remv, i >> 6);
        bool alive = k0 && !((sup >> (i & 63)) & 1ull);
        if (alive && lane < 16) remv |= m;
        if (lane == 0) g_keepf[i] = alive ? 1 : 0;
        m = nxt;
    }
}

// ---------------- kernel 5: compaction + output ----------------------------
__global__ void k_out(float* __restrict__ out, int out_size) {
    int t = threadIdx.x;  // 1024 threads
    for (int i = t; i < out_size; i += 1024) out[i] = 0.0f;
    __syncthreads();

    int k = g_keepf[t];
    unsigned ball = __ballot_sync(0xffffffffu, k);
    int lane = t & 31, w = t >> 5;
    __shared__ int ws[32];
    __shared__ int wx[32];
    if (lane == 0) ws[w] = __popc(ball);
    __syncthreads();
    if (t < 32) {
        int v = ws[t];
        int inc = v;
        #pragma unroll
        for (int o = 1; o < 32; o <<= 1) {
            int n = __shfl_up_sync(0xffffffffu, inc, o);
            if (t >= o) inc += n;
        }
        wx[t] = inc - v;  // exclusive
    }
    __syncthreads();
    int rank = wx[w] + __popc(ball & ((1u << lane) - 1u));
    if (k && rank < MAXDET) {
        float* row = out + rank * 6;
        row[0] = g_outb[t * 4 + 0];
        row[1] = g_outb[t * 4 + 1];
        row[2] = g_outb[t * 4 + 2];
        row[3] = g_outb[t * 4 + 3];
        row[4] = g_topconf[t];
        row[5] = g_cf[t];
    }
}

// ---------------- launcher -------------------------------------------------
extern "C" void kernel_launch(void* const* d_in, const int* in_sizes, int n_in,
                              void* d_out, int out_size) {
    const float* preds = (const float*)d_in[0];  // (32,84,8400); batch 0 only
    float* out = (float*)d_out;

    cudaFuncSetAttribute(k_sort, cudaFuncAttributeMaxDynamicSharedMemorySize,
                         NSORT * (int)sizeof(unsigned long long));

    k_prep<<<(NSORT + 255) / 256, 256>>>(preds);
    k_sort<<<1, SORT_THREADS, NSORT * sizeof(unsigned long long)>>>();
    k_mask<<<dim3(16, 16), 64>>>();
    k_serial<<<1, 32>>>();
    k_out<<<1, 1024>>>(out, out_size);
}

// round 5
// speedup vs baseline: 1.6434x; 1.6434x over previous
#include <cuda_runtime.h>

#define NPRED 8400
#define NCLS  80
#define NSORT 16384
#define NMSN  1024
#define MAXDET 300
#define SORT_THREADS 1024

// ---------------- scratch (device globals; no allocation allowed) ----------
__device__ float              g_conf[NPRED];
__device__ int                g_cls[NPRED];
__device__ float              g_box[NPRED * 4];
__device__ unsigned long long g_key[NSORT];

__device__ float g_topconf[NMSN];
__device__ float g_ob[NMSN * 4];    // class-offset boxes (for IoU)
__device__ float g_area[NMSN];
__device__ float g_outb[NMSN * 4];  // original boxes (for output)
__device__ float g_cf[NMSN];        // class as float
__device__ int   g_keep0[NMSN];
__device__ unsigned long long g_mask[NMSN * 16];

// ---------------- kernel 1: conf/argmax/boxes/sort-keys (batch 0 only) -----
__global__ void k_prep(const float* __restrict__ p) {
    int a = blockIdx.x * blockDim.x + threadIdx.x;
    if (a >= NSORT) return;
    if (a < NPRED) {
        float cx = p[0 * NPRED + a];
        float cy = p[1 * NPRED + a];
        float w  = p[2 * NPRED + a];
        float h  = p[3 * NPRED + a];
        float hw = __fmul_rn(w, 0.5f);
        float hh = __fmul_rn(h, 0.5f);
        g_box[a * 4 + 0] = __fsub_rn(cx, hw);
        g_box[a * 4 + 1] = __fsub_rn(cy, hh);
        g_box[a * 4 + 2] = __fadd_rn(cx, hw);
        g_box[a * 4 + 3] = __fadd_rn(cy, hh);

        float m = p[4 * NPRED + a];
        int cl = 0;
        #pragma unroll 4
        for (int c = 1; c < NCLS; ++c) {
            float v = p[(4 + c) * NPRED + a];
            if (v > m) { m = v; cl = c; }   // first-max tie-break (strict >)
        }
        g_conf[a] = m;
        g_cls[a]  = cl;

        float mc = (m > 0.25f) ? m : -1.0f;
        unsigned u = __float_as_uint(mc);
        u = (u & 0x80000000u) ? ~u : (u | 0x80000000u);  // monotone asc map
        unsigned k = ~u;                                  // descending conf
        g_key[a] = ((unsigned long long)k << 32) | (unsigned)a;
    } else {
        g_key[a] = 0xFFFFFFFFFFFFFFFFull;  // sentinel: sorts last
    }
}

// ---------------- kernel 2: bitonic sort (asc) + top-1024 gather -----------
__global__ void k_sort() {
    extern __shared__ unsigned long long sk[];
    int t = threadIdx.x;
    for (int i = t; i < NSORT; i += SORT_THREADS) sk[i] = g_key[i];
    __syncthreads();

    for (int size = 2; size <= NSORT; size <<= 1) {
        for (int stride = size >> 1; stride > 0; stride >>= 1) {
            for (int b = t; b < NSORT / 2; b += SORT_THREADS) {
                int low = b & (stride - 1);
                int i = ((b ^ low) << 1) | low;
                int j = i + stride;
                unsigned long long A = sk[i], B = sk[j];
                bool asc = ((i & size) == 0);
                if ((A > B) == asc) { sk[i] = B; sk[j] = A; }
            }
            __syncthreads();
        }
    }

    if (t < NMSN) {
        unsigned long long key = sk[t];
        int idx = (int)(key & 0xFFFFFFFFu);
        float tc = -1.0f, b0 = 0.f, b1 = 0.f, b2 = 0.f, b3 = 0.f, cf = 0.f;
        if (idx >= 0 && idx < NPRED) {
            float c = g_conf[idx];
            tc = (c > 0.25f) ? c : -1.0f;
            b0 = g_box[idx * 4 + 0];
            b1 = g_box[idx * 4 + 1];
            b2 = g_box[idx * 4 + 2];
            b3 = g_box[idx * 4 + 3];
            cf = (float)g_cls[idx];
        }
        g_topconf[t] = tc;
        g_keep0[t]   = (tc > 0.25f) ? 1 : 0;
        g_outb[t * 4 + 0] = b0;
        g_outb[t * 4 + 1] = b1;
        g_outb[t * 4 + 2] = b2;
        g_outb[t * 4 + 3] = b3;
        g_cf[t] = cf;

        float off = __fmul_rn(cf, 7680.0f);
        float o0 = __fadd_rn(b0, off);
        float o1 = __fadd_rn(b1, off);
        float o2 = __fadd_rn(b2, off);
        float o3 = __fadd_rn(b3, off);
        g_ob[t * 4 + 0] = o0;
        g_ob[t * 4 + 1] = o1;
        g_ob[t * 4 + 2] = o2;
        g_ob[t * 4 + 3] = o3;
        // area on OFFSET boxes (matches reference's quantized arithmetic)
        g_area[t] = __fmul_rn(__fsub_rn(o2, o0), __fsub_rn(o3, o1));
    }
}

// ---------------- kernel 3: 1024x1024 IoU suppression bitmask --------------
__global__ void k_mask() {
    __shared__ float sx1[64], sy1[64], sx2[64], sy2[64], sa[64];
    int t = threadIdx.x;                 // 0..63
    int col0 = blockIdx.x * 64;
    int r = blockIdx.y * 64 + t;
    int j = col0 + t;
    sx1[t] = g_ob[j * 4 + 0];
    sy1[t] = g_ob[j * 4 + 1];
    sx2[t] = g_ob[j * 4 + 2];
    sy2[t] = g_ob[j * 4 + 3];
    sa[t]  = g_area[j];
    __syncthreads();

    float x1 = g_ob[r * 4 + 0];
    float y1 = g_ob[r * 4 + 1];
    float x2 = g_ob[r * 4 + 2];
    float y2 = g_ob[r * 4 + 3];
    float ar = g_area[r];

    unsigned long long bits = 0ull;
    #pragma unroll 8
    for (int jj = 0; jj < 64; ++jj) {
        int cidx = col0 + jj;
        if (cidx <= r) continue;
        float lx = fmaxf(x1, sx1[jj]);
        float ly = fmaxf(y1, sy1[jj]);
        float rx = fminf(x2, sx2[jj]);
        float ry = fminf(y2, sy2[jj]);
        float ww = fmaxf(__fsub_rn(rx, lx), 0.0f);
        float hh = fmaxf(__fsub_rn(ry, ly), 0.0f);
        float inter = __fmul_rn(ww, hh);
        float den = __fadd_rn(__fsub_rn(__fadd_rn(ar, sa[jj]), inter), 1e-7f);
        float iou = __fdiv_rn(inter, den);
        if (iou > 0.45f) bits |= (1ull << jj);
    }
    g_mask[r * 16 + blockIdx.x] = bits;
}

// ---------------- kernel 4: blocked greedy NMS + compaction + output -------
// Whole 1024x1024 mask (128 KB) lives in shared memory. One warp runs the
// greedy pass in 16 blocks of 64: lane `blk` runs the 64-step serial chain
// against the diagonal sub-block (register/LDS only, ~8 cyc/step), then a
// single shfl broadcasts the alive bits and 16 lanes OR the alive rows into
// their remv words branchlessly. Identical bit semantics to the reference
// fori_loop. Output compaction is fused at the end.
__global__ void k_final(float* __restrict__ out, int out_size) {
    extern __shared__ unsigned long long smask[];   // NMSN*16 u64 = 128 KB
    __shared__ unsigned int       skeep32[32];
    __shared__ unsigned long long salive[16];
    __shared__ int ws[32], wx[32];

    int t = threadIdx.x;  // 1024 threads

    // Phase 1: stage mask into smem, pack keep0, zero output
    {
        const ulonglong2* gm = (const ulonglong2*)g_mask;
        ulonglong2* sm2 = (ulonglong2*)smask;
        #pragma unroll
        for (int i = 0; i < (NMSN * 16 / 2) / 1024; ++i)
            sm2[t + i * 1024] = gm[t + i * 1024];
    }
    {
        int k0 = g_keep0[t];
        unsigned ball = __ballot_sync(0xffffffffu, k0);
        if ((t & 31) == 0) skeep32[t >> 5] = ball;
    }
    for (int i = t; i < out_size; i += 1024) out[i] = 0.0f;
    __syncthreads();

    // Phase 2: one warp, blocked greedy pass
    if (t < 32) {
        int lane = t;
        unsigned long long remv = 0ull;
        for (int blk = 0; blk < 16; ++blk) {
            unsigned long long alive = 0ull;
            if (lane == blk) {
                unsigned long long sup = remv;
                unsigned long long k0w =
                    ((unsigned long long)skeep32[blk * 2 + 1] << 32) |
                    (unsigned long long)skeep32[blk * 2];
                const unsigned long long* diag = smask + (blk * 64) * 16 + blk;
                #pragma unroll 16
                for (int j = 0; j < 64; ++j) {
                    unsigned long long w = diag[j * 16];
                    bool a = ((k0w >> j) & 1ull) && !((sup >> j) & 1ull);
                    if (a) { alive |= (1ull << j); sup |= w; }
                }
            }
            alive = __shfl_sync(0xffffffffu, alive, blk);
            if (lane < 16) {
                const unsigned long long* rowp = smask + (blk * 64) * 16 + lane;
                #pragma unroll 16
                for (int j = 0; j < 64; ++j) {
                    unsigned long long sel =
                        (unsigned long long)(-(long long)((alive >> j) & 1ull));
                    remv |= (rowp[j * 16] & sel);
                }
            }
            if (lane == blk) salive[blk] = alive;
        }
    }
    __syncthreads();

    // Phase 3: compaction + output (kept candidates are already conf-sorted)
    int alivebit = (int)((salive[t >> 6] >> (t & 63)) & 1ull);
    unsigned b2 = __ballot_sync(0xffffffffu, alivebit);
    int lane = t & 31, w = t >> 5;
    if (lane == 0) ws[w] = __popc(b2);
    __syncthreads();
    if (t < 32) {
        int v = ws[t];
        int inc = v;
        #pragma unroll
        for (int o = 1; o < 32; o <<= 1) {
            int n = __shfl_up_sync(0xffffffffu, inc, o);
            if (t >= o) inc += n;
        }
        wx[t] = inc - v;  // exclusive
    }
    __syncthreads();
    int rank = wx[w] + __popc(b2 & ((1u << lane) - 1u));
    if (alivebit && rank < MAXDET) {
        float* row = out + rank * 6;
        row[0] = g_outb[t * 4 + 0];
        row[1] = g_outb[t * 4 + 1];
        row[2] = g_outb[t * 4 + 2];
        row[3] = g_outb[t * 4 + 3];
        row[4] = g_topconf[t];
        row[5] = g_cf[t];
    }
}

// ---------------- launcher -------------------------------------------------
extern "C" void kernel_launch(void* const* d_in, const int* in_sizes, int n_in,
                              void* d_out, int out_size) {
    const float* preds = (const float*)d_in[0];  // (32,84,8400); batch 0 only
    float* out = (float*)d_out;

    cudaFuncSetAttribute(k_sort, cudaFuncAttributeMaxDynamicSharedMemorySize,
                         NSORT * (int)sizeof(unsigned long long));
    cudaFuncSetAttribute(k_final, cudaFuncAttributeMaxDynamicSharedMemorySize,
                         NMSN * 16 * (int)sizeof(unsigned long long));

    k_prep<<<(NSORT + 255) / 256, 256>>>(preds);
    k_sort<<<1, SORT_THREADS, NSORT * sizeof(unsigned long long)>>>();
    k_mask<<<dim3(16, 16), 64>>>();
    k_final<<<1, 1024, NMSN * 16 * sizeof(unsigned long long)>>>(out, out_size);
}

// round 6
// speedup vs baseline: 4.2737x; 2.6005x over previous
#include <cuda_runtime.h>

#define NPRED 8400
#define NCLS  80
#define NSORT 16384
#define NMSN  1024
#define MAXDET 300

// ---------------- scratch (device globals; no allocation allowed) ----------
__device__ float              g_conf[NPRED];
__device__ int                g_cls[NPRED];
__device__ float              g_box[NPRED * 4];
__device__ unsigned long long g_skey[NSORT];   // 16 sorted chunks of 1024

__device__ float g_topconf[NMSN];
__device__ float g_ob[NMSN * 4];    // class-offset boxes (for IoU)
__device__ float g_area[NMSN];
__device__ float g_outb[NMSN * 4];  // original boxes (for output)
__device__ float g_cf[NMSN];        // class as float
__device__ int   g_keep0[NMSN];
__device__ unsigned long long g_mask[NMSN * 16];

// ---------------- kernel 1: fused prep + per-chunk bitonic sort ------------
// 16 blocks x 512 threads. Block c handles anchors [c*1024, (c+1)*1024):
// computes boxes/conf/cls/sort-keys, then sorts its 1024 keys ascending
// in shared memory and writes the sorted chunk to g_skey.
__global__ void k_prepsort(const float* __restrict__ p) {
    __shared__ unsigned long long sk[1024];
    int c = blockIdx.x;
    int t = threadIdx.x;  // 0..511

    #pragma unroll
    for (int e = 0; e < 2; ++e) {
        int local = t + e * 512;
        int a = c * 1024 + local;
        unsigned long long key = 0xFFFFFFFFFFFFFFFFull;  // sentinel
        if (a < NPRED) {
            float cx = p[0 * NPRED + a];
            float cy = p[1 * NPRED + a];
            float w  = p[2 * NPRED + a];
            float h  = p[3 * NPRED + a];
            float hw = __fmul_rn(w, 0.5f);
            float hh = __fmul_rn(h, 0.5f);
            g_box[a * 4 + 0] = __fsub_rn(cx, hw);
            g_box[a * 4 + 1] = __fsub_rn(cy, hh);
            g_box[a * 4 + 2] = __fadd_rn(cx, hw);
            g_box[a * 4 + 3] = __fadd_rn(cy, hh);

            float m = p[4 * NPRED + a];
            int cl = 0;
            #pragma unroll 4
            for (int cc = 1; cc < NCLS; ++cc) {
                float v = p[(4 + cc) * NPRED + a];
                if (v > m) { m = v; cl = cc; }   // first-max tie-break
            }
            g_conf[a] = m;
            g_cls[a]  = cl;

            float mc = (m > 0.25f) ? m : -1.0f;
            unsigned u = __float_as_uint(mc);
            u = (u & 0x80000000u) ? ~u : (u | 0x80000000u);  // monotone asc
            unsigned k = ~u;                                  // desc conf
            key = ((unsigned long long)k << 32) | (unsigned)a;
        }
        sk[local] = key;
    }
    __syncthreads();

    // bitonic sort of 1024 keys, ascending; 512 compare-exchanges per pass
    for (int size = 2; size <= 1024; size <<= 1) {
        for (int stride = size >> 1; stride > 0; stride >>= 1) {
            int low = t & (stride - 1);
            int i = ((t ^ low) << 1) | low;
            int j = i + stride;
            unsigned long long A = sk[i], B = sk[j];
            bool asc = ((i & size) == 0);
            if ((A > B) == asc) { sk[i] = B; sk[j] = A; }
            __syncthreads();
        }
    }

    g_skey[c * 1024 + t]       = sk[t];
    g_skey[c * 1024 + t + 512] = sk[t + 512];
}

// ---------------- kernel 2: tournament min-merge + top-1024 gather ---------
// One block, 1024 threads, all 16 sorted chunks staged in 128 KB smem.
// Level L merges pairs of ascending 1024-lists: C[i]=min(A[i],B[1023-i])
// keeps the global smallest 1024 (bitonic), then 10 cleanup passes sort it.
__global__ void k_merge() {
    extern __shared__ unsigned long long s[];   // NSORT u64 = 128 KB
    int t = threadIdx.x;  // 0..1023

    #pragma unroll
    for (int i = 0; i < NSORT / 1024; ++i) s[t + i * 1024] = g_skey[t + i * 1024];
    __syncthreads();

    #pragma unroll
    for (int L = 1; L <= 4; ++L) {
        int half   = 1024 << (L - 1);
        int npairs = 16 >> L;
        // min step
        for (int w = t; w < npairs * 1024; w += 1024) {
            int pr = w >> 10, i = w & 1023;
            int A = pr * (half * 2);
            unsigned long long a = s[A + i], b = s[A + half + 1023 - i];
            s[A + i] = (a < b) ? a : b;
        }
        __syncthreads();
        // cleanup: sort each surviving bitonic 1024-segment ascending
        for (int stride = 512; stride > 0; stride >>= 1) {
            int nce = npairs * 512;
            for (int w = t; w < nce; w += 1024) {
                int pr = w / 512, b2 = w % 512;
                int low = b2 & (stride - 1);
                int i = ((b2 ^ low) << 1) | low;
                int x = pr * (half * 2) + i;
                int y = x + stride;
                unsigned long long A2 = s[x], B2 = s[y];
                if (A2 > B2) { s[x] = B2; s[y] = A2; }
            }
            __syncthreads();
        }
    }

    // epilogue: gather top-1024 candidate data (identical to prior k_sort)
    {
        unsigned long long key = s[t];
        int idx = (int)(key & 0xFFFFFFFFu);
        float tc = -1.0f, b0 = 0.f, b1 = 0.f, b2 = 0.f, b3 = 0.f, cf = 0.f;
        if (idx >= 0 && idx < NPRED) {
            float c = g_conf[idx];
            tc = (c > 0.25f) ? c : -1.0f;
            b0 = g_box[idx * 4 + 0];
            b1 = g_box[idx * 4 + 1];
            b2 = g_box[idx * 4 + 2];
            b3 = g_box[idx * 4 + 3];
            cf = (float)g_cls[idx];
        }
        g_topconf[t] = tc;
        g_keep0[t]   = (tc > 0.25f) ? 1 : 0;
        g_outb[t * 4 + 0] = b0;
        g_outb[t * 4 + 1] = b1;
        g_outb[t * 4 + 2] = b2;
        g_outb[t * 4 + 3] = b3;
        g_cf[t] = cf;

        float off = __fmul_rn(cf, 7680.0f);
        float o0 = __fadd_rn(b0, off);
        float o1 = __fadd_rn(b1, off);
        float o2 = __fadd_rn(b2, off);
        float o3 = __fadd_rn(b3, off);
        g_ob[t * 4 + 0] = o0;
        g_ob[t * 4 + 1] = o1;
        g_ob[t * 4 + 2] = o2;
        g_ob[t * 4 + 3] = o3;
        g_area[t] = __fmul_rn(__fsub_rn(o2, o0), __fsub_rn(o3, o1));
    }
}

// ---------------- kernel 3: 1024x1024 IoU suppression bitmask --------------
__global__ void k_mask() {
    __shared__ float sx1[64], sy1[64], sx2[64], sy2[64], sa[64];
    int t = threadIdx.x;                 // 0..63
    int col0 = blockIdx.x * 64;
    int r = blockIdx.y * 64 + t;
    int j = col0 + t;
    sx1[t] = g_ob[j * 4 + 0];
    sy1[t] = g_ob[j * 4 + 1];
    sx2[t] = g_ob[j * 4 + 2];
    sy2[t] = g_ob[j * 4 + 3];
    sa[t]  = g_area[j];
    __syncthreads();

    float x1 = g_ob[r * 4 + 0];
    float y1 = g_ob[r * 4 + 1];
    float x2 = g_ob[r * 4 + 2];
    float y2 = g_ob[r * 4 + 3];
    float ar = g_area[r];

    unsigned long long bits = 0ull;
    #pragma unroll 8
    for (int jj = 0; jj < 64; ++jj) {
        int cidx = col0 + jj;
        if (cidx <= r) continue;
        float lx = fmaxf(x1, sx1[jj]);
        float ly = fmaxf(y1, sy1[jj]);
        float rx = fminf(x2, sx2[jj]);
        float ry = fminf(y2, sy2[jj]);
        float ww = fmaxf(__fsub_rn(rx, lx), 0.0f);
        float hh = fmaxf(__fsub_rn(ry, ly), 0.0f);
        float inter = __fmul_rn(ww, hh);
        float den = __fadd_rn(__fsub_rn(__fadd_rn(ar, sa[jj]), inter), 1e-7f);
        float iou = __fdiv_rn(inter, den);
        if (iou > 0.45f) bits |= (1ull << jj);
    }
    g_mask[r * 16 + blockIdx.x] = bits;
}

// ---------------- kernel 4: blocked greedy NMS + compaction + output -------
__global__ void k_final(float* __restrict__ out, int out_size) {
    extern __shared__ unsigned long long smask[];   // NMSN*16 u64 = 128 KB
    __shared__ unsigned int       skeep32[32];
    __shared__ unsigned long long salive[16];
    __shared__ int ws[32], wx[32];

    int t = threadIdx.x;  // 1024 threads

    // Phase 1: stage mask into smem, pack keep0, zero output
    {
        const ulonglong2* gm = (const ulonglong2*)g_mask;
        ulonglong2* sm2 = (ulonglong2*)smask;
        #pragma unroll
        for (int i = 0; i < (NMSN * 16 / 2) / 1024; ++i)
            sm2[t + i * 1024] = gm[t + i * 1024];
    }
    {
        int k0 = g_keep0[t];
        unsigned ball = __ballot_sync(0xffffffffu, k0);
        if ((t & 31) == 0) skeep32[t >> 5] = ball;
    }
    for (int i = t; i < out_size; i += 1024) out[i] = 0.0f;
    __syncthreads();

    // Phase 2: one warp, blocked greedy pass (branchless diagonal chain)
    if (t < 32) {
        int lane = t;
        unsigned long long remv = 0ull;
        for (int blk = 0; blk < 16; ++blk) {
            unsigned long long alive = 0ull;
            if (lane == blk) {
                unsigned long long sup = remv;
                unsigned long long k0w =
                    ((unsigned long long)skeep32[blk * 2 + 1] << 32) |
                    (unsigned long long)skeep32[blk * 2];
                const unsigned long long* diag = smask + (blk * 64) * 16 + blk;
                #pragma unroll 16
                for (int j = 0; j < 64; ++j) {
                    unsigned long long w = diag[j * 16];
                    unsigned long long a = (k0w & ~sup) & (1ull << j);
                    unsigned long long sel =
                        (unsigned long long)(-(long long)((a >> j) & 1ull));
                    alive |= a;
                    sup   |= (w & sel);
                }
            }
            alive = __shfl_sync(0xffffffffu, alive, blk);
            if (lane < 16) {
                const unsigned long long* rowp = smask + (blk * 64) * 16 + lane;
                #pragma unroll 16
                for (int j = 0; j < 64; ++j) {
                    unsigned long long sel =
                        (unsigned long long)(-(long long)((alive >> j) & 1ull));
                    remv |= (rowp[j * 16] & sel);
                }
            }
            if (lane == blk) salive[blk] = alive;
        }
    }
    __syncthreads();

    // Phase 3: compaction + output (kept candidates already conf-sorted)
    int alivebit = (int)((salive[t >> 6] >> (t & 63)) & 1ull);
    unsigned b2 = __ballot_sync(0xffffffffu, alivebit);
    int lane = t & 31, w = t >> 5;
    if (lane == 0) ws[w] = __popc(b2);
    __syncthreads();
    if (t < 32) {
        int v = ws[t];
        int inc = v;
        #pragma unroll
        for (int o = 1; o < 32; o <<= 1) {
            int n = __shfl_up_sync(0xffffffffu, inc, o);
            if (t >= o) inc += n;
        }
        wx[t] = inc - v;  // exclusive
    }
    __syncthreads();
    int rank = wx[w] + __popc(b2 & ((1u << lane) - 1u));
    if (alivebit && rank < MAXDET) {
        float* row = out + rank * 6;
        row[0] = g_outb[t * 4 + 0];
        row[1] = g_outb[t * 4 + 1];
        row[2] = g_outb[t * 4 + 2];
        row[3] = g_outb[t * 4 + 3];
        row[4] = g_topconf[t];
        row[5] = g_cf[t];
    }
}

// ---------------- launcher -------------------------------------------------
extern "C" void kernel_launch(void* const* d_in, const int* in_sizes, int n_in,
                              void* d_out, int out_size) {
    const float* preds = (const float*)d_in[0];  // (32,84,8400); batch 0 only
    float* out = (float*)d_out;

    cudaFuncSetAttribute(k_merge, cudaFuncAttributeMaxDynamicSharedMemorySize,
                         NSORT * (int)sizeof(unsigned long long));
    cudaFuncSetAttribute(k_final, cudaFuncAttributeMaxDynamicSharedMemorySize,
                         NMSN * 16 * (int)sizeof(unsigned long long));

    k_prepsort<<<16, 512>>>(preds);
    k_merge<<<1, 1024, NSORT * sizeof(unsigned long long)>>>();
    k_mask<<<dim3(16, 16), 64>>>();
    k_final<<<1, 1024, NMSN * 16 * sizeof(unsigned long long)>>>(out, out_size);
}

// round 8
// speedup vs baseline: 5.0960x; 1.1924x over previous
#include <cuda_runtime.h>

#define NPRED 8400
#define NCLS  80
#define NSORT 16384
#define NMSN  1024
#define MAXDET 300

// ---------------- scratch (device globals; no allocation allowed) ----------
__device__ float              g_conf[NPRED];
__device__ int                g_cls[NPRED];
__device__ float              g_box[NPRED * 4];
__device__ unsigned long long g_skey[NSORT];   // 16 sorted chunks of 1024

// ---------------- kernel 1: fused prep + per-chunk bitonic sort ------------
__global__ void k_prepsort(const float* __restrict__ p) {
    __shared__ unsigned long long sk[1024];
    int c = blockIdx.x;
    int t = threadIdx.x;  // 0..511

    #pragma unroll
    for (int e = 0; e < 2; ++e) {
        int local = t + e * 512;
        int a = c * 1024 + local;
        unsigned long long key = 0xFFFFFFFFFFFFFFFFull;  // sentinel
        if (a < NPRED) {
            float cx = p[0 * NPRED + a];
            float cy = p[1 * NPRED + a];
            float w  = p[2 * NPRED + a];
            float h  = p[3 * NPRED + a];
            float hw = __fmul_rn(w, 0.5f);
            float hh = __fmul_rn(h, 0.5f);
            g_box[a * 4 + 0] = __fsub_rn(cx, hw);
            g_box[a * 4 + 1] = __fsub_rn(cy, hh);
            g_box[a * 4 + 2] = __fadd_rn(cx, hw);
            g_box[a * 4 + 3] = __fadd_rn(cy, hh);

            float m = p[4 * NPRED + a];
            int cl = 0;
            #pragma unroll 4
            for (int cc = 1; cc < NCLS; ++cc) {
                float v = p[(4 + cc) * NPRED + a];
                if (v > m) { m = v; cl = cc; }   // first-max tie-break
            }
            g_conf[a] = m;
            g_cls[a]  = cl;

            float mc = (m > 0.25f) ? m : -1.0f;
            unsigned u = __float_as_uint(mc);
            u = (u & 0x80000000u) ? ~u : (u | 0x80000000u);  // monotone asc
            unsigned k = ~u;                                  // desc conf
            key = ((unsigned long long)k << 32) | (unsigned)a;
        }
        sk[local] = key;
    }
    __syncthreads();

    for (int size = 2; size <= 1024; size <<= 1) {
        for (int stride = size >> 1; stride > 0; stride >>= 1) {
            int low = t & (stride - 1);
            int i = ((t ^ low) << 1) | low;
            int j = i + stride;
            unsigned long long A = sk[i], B = sk[j];
            bool asc = ((i & size) == 0);
            if ((A > B) == asc) { sk[i] = B; sk[j] = A; }
            __syncthreads();
        }
    }

    g_skey[c * 1024 + t]       = sk[t];
    g_skey[c * 1024 + t + 512] = sk[t + 512];
}

// ---------------- kernel 2: merge + gather + per-class NMS + output --------
// One block, 1024 threads, 128 KB dynamic smem.
//  a) tournament min-merge of 16 sorted chunks -> global top-1024 (sorted)
//  b) gather candidate data into the (now free) upper smem region
//  c) per-class greedy NMS: cross-class IoU is exactly 0 (cls*7680 offset,
//     areas >= 0), so the reference's serial chain decomposes exactly into
//     80 independent per-class chains. 32 warps each own <=3 classes.
//  d) ballot-scan compaction + output (kept entries already conf-sorted)
__global__ void k_all(float* __restrict__ out, int out_size) {
    extern __shared__ unsigned char dyn[];
    unsigned long long* s = (unsigned long long*)dyn;        // [0, 131072)
    float* s_ob   = (float*)(dyn + 8192);    // 4096 f: offset boxes (float4)
    float* s_area = (float*)(dyn + 24576);   // 1024 f
    float* s_outb = (float*)(dyn + 28672);   // 4096 f: original boxes
    float* s_tc   = (float*)(dyn + 45056);   // 1024 f
    int*   s_cls  = (int*)(dyn + 49152);     // 1024
    int*   s_keep = (int*)(dyn + 53248);     // 1024
    int*   s_list = (int*)(dyn + 57344);     // 1024
    int*   s_cnt  = (int*)(dyn + 61440);     // 80
    int*   s_off  = (int*)(dyn + 61760);     // 80
    __shared__ int ws[32], wx[32];

    int t = threadIdx.x;  // 0..1023
    int w = t >> 5, lane = t & 31;

    // ---- a) load keys + tournament min-merge (identical to prior k_merge)
    #pragma unroll
    for (int i = 0; i < NSORT / 1024; ++i) s[t + i * 1024] = g_skey[t + i * 1024];
    __syncthreads();

    #pragma unroll
    for (int L = 1; L <= 4; ++L) {
        int half   = 1024 << (L - 1);
        int npairs = 16 >> L;
        for (int q = t; q < npairs * 1024; q += 1024) {
            int pr = q >> 10, i = q & 1023;
            int A = pr * (half * 2);
            unsigned long long a = s[A + i], b = s[A + half + 1023 - i];
            s[A + i] = (a < b) ? a : b;
        }
        __syncthreads();
        for (int stride = 512; stride > 0; stride >>= 1) {
            int nce = npairs * 512;
            for (int q = t; q < nce; q += 1024) {
                int pr = q / 512, b2 = q % 512;
                int low = b2 & (stride - 1);
                int i = ((b2 ^ low) << 1) | low;
                int x = pr * (half * 2) + i;
                int y = x + stride;
                unsigned long long A2 = s[x], B2 = s[y];
                if (A2 > B2) { s[x] = B2; s[y] = A2; }
            }
            __syncthreads();
        }
    }

    // ---- b) gather top-1024 candidate data into smem; zero output
    {
        unsigned long long key = s[t];
        int idx = (int)(key & 0xFFFFFFFFu);
        float tc = -1.0f, b0 = 0.f, b1 = 0.f, b2 = 0.f, b3 = 0.f;
        int cl = 0;
        if (idx >= 0 && idx < NPRED) {
            float c = g_conf[idx];
            tc = (c > 0.25f) ? c : -1.0f;
            b0 = g_box[idx * 4 + 0];
            b1 = g_box[idx * 4 + 1];
            b2 = g_box[idx * 4 + 2];
            b3 = g_box[idx * 4 + 3];
            cl = g_cls[idx];
        }
        s_tc[t]   = tc;
        s_keep[t] = (tc > 0.25f) ? 1 : 0;
        s_cls[t]  = cl;
        s_outb[t * 4 + 0] = b0;
        s_outb[t * 4 + 1] = b1;
        s_outb[t * 4 + 2] = b2;
        s_outb[t * 4 + 3] = b3;

        float off = __fmul_rn((float)cl, 7680.0f);
        float o0 = __fadd_rn(b0, off);
        float o1 = __fadd_rn(b1, off);
        float o2 = __fadd_rn(b2, off);
        float o3 = __fadd_rn(b3, off);
        s_ob[t * 4 + 0] = o0;
        s_ob[t * 4 + 1] = o1;
        s_ob[t * 4 + 2] = o2;
        s_ob[t * 4 + 3] = o3;
        s_area[t] = __fmul_rn(__fsub_rn(o2, o0), __fsub_rn(o3, o1));
    }
    for (int i = t; i < out_size; i += 1024) out[i] = 0.0f;
    __syncthreads();

    // ---- c1) per-class counts (warp w owns classes w, w+32, w+64)
    for (int c = w; c < NCLS; c += 32) {
        int cntc = 0;
        #pragma unroll 4
        for (int k = 0; k < 32; ++k) {
            int p = k * 32 + lane;
            int m = (s_cls[p] == c) && s_keep[p];
            unsigned b = __ballot_sync(0xffffffffu, m);
            cntc += __popc(b);
        }
        if (lane == 0) s_cnt[c] = cntc;
    }
    __syncthreads();

    // ---- c2) exclusive prefix scan of 80 counts (warp 0)
    if (t < 32) {
        int v0 = s_cnt[t];
        int v1 = s_cnt[32 + t];
        int v2 = (t < 16) ? s_cnt[64 + t] : 0;
        int s0 = v0, s1 = v1, s2 = v2;
        #pragma unroll
        for (int o = 1; o < 32; o <<= 1) {
            int n0 = __shfl_up_sync(0xffffffffu, s0, o);
            int n1 = __shfl_up_sync(0xffffffffu, s1, o);
            int n2 = __shfl_up_sync(0xffffffffu, s2, o);
            if (t >= o) { s0 += n0; s1 += n1; s2 += n2; }
        }
        int tot0 = __shfl_sync(0xffffffffu, s0, 31);
        int tot1 = __shfl_sync(0xffffffffu, s1, 31);
        s_off[t] = s0 - v0;
        s_off[32 + t] = tot0 + s1 - v1;
        if (t < 16) s_off[64 + t] = tot0 + tot1 + s2 - v2;
    }
    __syncthreads();

    // ---- c3) fill class list + per-class greedy NMS chain
    const float4* ob4 = (const float4*)s_ob;
    for (int c = w; c < NCLS; c += 32) {
        int base = s_off[c];
        int run = base;
        #pragma unroll 4
        for (int k = 0; k < 32; ++k) {
            int p = k * 32 + lane;
            int m = (s_cls[p] == c) && s_keep[p];
            unsigned b = __ballot_sync(0xffffffffu, m);
            if (m) s_list[run + __popc(b & ((1u << lane) - 1u))] = p;
            run += __popc(b);
        }
        int n = run - base;
        __syncwarp();
        for (int i = 0; i < n; ++i) {
            int pi = s_list[base + i];
            int alive = s_keep[pi];      // broadcast smem read
            if (alive) {
                float4 bi = ob4[pi];
                float  ai = s_area[pi];
                for (int m2 = i + 1 + lane; m2 < n; m2 += 32) {
                    int pm = s_list[base + m2];
                    float4 bj = ob4[pm];
                    float lx = fmaxf(bi.x, bj.x);
                    float ly = fmaxf(bi.y, bj.y);
                    float rx = fminf(bi.z, bj.z);
                    float ry = fminf(bi.w, bj.w);
                    float ww = fmaxf(__fsub_rn(rx, lx), 0.0f);
                    float hh = fmaxf(__fsub_rn(ry, ly), 0.0f);
                    float inter = __fmul_rn(ww, hh);
                    float den = __fadd_rn(
                        __fsub_rn(__fadd_rn(ai, s_area[pm]), inter), 1e-7f);
                    if (__fdiv_rn(inter, den) > 0.45f) s_keep[pm] = 0;
                }
            }
            __syncwarp();
        }
    }
    __syncthreads();

    // ---- d) compaction + output (kept candidates already conf-sorted)
    int alivebit = s_keep[t];
    unsigned b2 = __ballot_sync(0xffffffffu, alivebit);
    if (lane == 0) ws[w] = __popc(b2);
    __syncthreads();
    if (t < 32) {
        int v = ws[t];
        int inc = v;
        #pragma unroll
        for (int o = 1; o < 32; o <<= 1) {
            int n = __shfl_up_sync(0xffffffffu, inc, o);
            if (t >= o) inc += n;
        }
        wx[t] = inc - v;  // exclusive
    }
    __syncthreads();
    int rank = wx[w] + __popc(b2 & ((1u << lane) - 1u));
    if (alivebit && rank < MAXDET) {
        float* row = out + rank * 6;
        row[0] = s_outb[t * 4 + 0];
        row[1] = s_outb[t * 4 + 1];
        row[2] = s_outb[t * 4 + 2];
        row[3] = s_outb[t * 4 + 3];
        row[4] = s_tc[t];
        row[5] = (float)s_cls[t];
    }
}

// ---------------- launcher -------------------------------------------------
extern "C" void kernel_launch(void* const* d_in, const int* in_sizes, int n_in,
                              void* d_out, int out_size) {
    const float* preds = (const float*)d_in[0];  // (32,84,8400); batch 0 only
    float* out = (float*)d_out;

    cudaFuncSetAttribute(k_all, cudaFuncAttributeMaxDynamicSharedMemorySize,
                         NSORT * (int)sizeof(unsigned long long));

    k_prepsort<<<16, 512>>>(preds);
    k_all<<<1, 1024, NSORT * sizeof(unsigned long long)>>>(out, out_size);
}

// round 14
// speedup vs baseline: 5.7865x; 1.1355x over previous
#include <cuda_runtime.h>

#define NPRED 8400
#define NCLS  80
#define NSORT 16384
#define MAXDET 300

// ---------------- scratch (device globals; no allocation allowed) ----------
__device__ float4             g_box4[NPRED];
__device__ unsigned long long g_skey[NSORT];   // 16 sorted chunks of 1024

// ---------------- kernel 1: fused prep + per-chunk bitonic sort ------------
// Key = (conf-key32 << 32) | (idx << 7) | cls.  idx-major low bits preserve
// the reference tie-break (equal conf -> lower idx first); masked conf is
// bit-exactly recoverable from key32, so no g_conf/g_cls arrays needed.
__global__ __launch_bounds__(512) void k_prepsort(const float* __restrict__ p) {
    __shared__ unsigned long long sk[1024];
    int c = blockIdx.x;
    int t = threadIdx.x;  // 0..511

    #pragma unroll
    for (int e = 0; e < 2; ++e) {
        int local = t + e * 512;
        int a = c * 1024 + local;
        unsigned long long key = 0xFFFFFFFFFFFFFFFFull;  // sentinel
        if (a < NPRED) {
            float cx = p[0 * NPRED + a];
            float cy = p[1 * NPRED + a];
            float w  = p[2 * NPRED + a];
            float h  = p[3 * NPRED + a];
            float hw = __fmul_rn(w, 0.5f);
            float hh = __fmul_rn(h, 0.5f);
            float4 b4;
            b4.x = __fsub_rn(cx, hw);
            b4.y = __fsub_rn(cy, hh);
            b4.z = __fadd_rn(cx, hw);
            b4.w = __fadd_rn(cy, hh);
            g_box4[a] = b4;

            float m = p[4 * NPRED + a];
            int cl = 0;
            #pragma unroll 16
            for (int cc = 1; cc < NCLS; ++cc) {
                float v = p[(4 + cc) * NPRED + a];
                if (v > m) { m = v; cl = cc; }   // first-max tie-break
            }
            float mc = (m > 0.25f) ? m : -1.0f;
            unsigned u = __float_as_uint(mc);
            u = (u & 0x80000000u) ? ~u : (u | 0x80000000u);  // monotone asc
            unsigned k = ~u;                                  // desc conf
            key = ((unsigned long long)k << 32) |
                  ((unsigned)a << 7) | (unsigned)cl;
        }
        sk[local] = key;
    }
    __syncthreads();

    // bitonic sort of 1024 keys, ascending (full barriers — proven structure)
    for (int size = 2; size <= 1024; size <<= 1) {
        for (int stride = size >> 1; stride > 0; stride >>= 1) {
            int low = t & (stride - 1);
            int i = ((t ^ low) << 1) | low;
            int j = i + stride;
            unsigned long long A = sk[i], B = sk[j];
            bool asc = ((i & size) == 0);
            if ((A > B) == asc) { sk[i] = B; sk[j] = A; }
            __syncthreads();
        }
    }

    g_skey[c * 1024 + t]       = sk[t];
    g_skey[c * 1024 + t + 512] = sk[t + 512];
}

// ---------------- kernel 2: merge + gather + per-class NMS + output --------
__global__ __launch_bounds__(1024) void k_all(float* __restrict__ out, int out_size) {
    extern __shared__ unsigned char dyn[];
    unsigned long long* s = (unsigned long long*)dyn;        // [0, 131072)
    float4*  s_ob4   = (float4*)(dyn + 8192);     // 1024 f4: offset boxes
    float*   s_area  = (float*)(dyn + 24576);     // 1024 f
    float4*  s_outb4 = (float4*)(dyn + 28672);    // 1024 f4: original boxes
    float*   s_tc    = (float*)(dyn + 45056);     // 1024 f
    int*     s_cls   = (int*)(dyn + 49152);       // 1024
    int*     s_keep  = (int*)(dyn + 53248);       // 1024
    int*     s_list  = (int*)(dyn + 57344);       // 1024
    int*     s_cnt   = (int*)(dyn + 61440);       // 80
    int*     s_off   = (int*)(dyn + 61760);       // 80
    unsigned* s_ball = (unsigned*)(dyn + 62080);  // 80*32 ballot cache
    __shared__ int ws[32], wx[32];

    int t = threadIdx.x;  // 0..1023
    int w = t >> 5, lane = t & 31;

    // ---- a) load keys + tournament min-merge (R8-proven: full barriers)
    #pragma unroll
    for (int i = 0; i < NSORT / 1024; ++i) s[t + i * 1024] = g_skey[t + i * 1024];
    __syncthreads();

    #pragma unroll
    for (int L = 1; L <= 4; ++L) {
        int half   = 1024 << (L - 1);
        int npairs = 16 >> L;
        // min step: C[i] = min(A[i], B[1023-i]) keeps global top-1024 (bitonic)
        for (int q = t; q < npairs * 1024; q += 1024) {
            int pr = q >> 10, i = q & 1023;
            int A = pr * (half * 2);
            unsigned long long a = s[A + i], b = s[A + half + 1023 - i];
            s[A + i] = (a < b) ? a : b;
        }
        __syncthreads();
        // cleanup: sort each surviving bitonic 1024-segment ascending
        for (int stride = 512; stride > 0; stride >>= 1) {
            int nce = npairs * 512;
            for (int q = t; q < nce; q += 1024) {
                int pr = q / 512, b2 = q % 512;
                int low = b2 & (stride - 1);
                int i = ((b2 ^ low) << 1) | low;
                int x = pr * (half * 2) + i;
                int y = x + stride;
                unsigned long long A2 = s[x], B2 = s[y];
                if (A2 > B2) { s[x] = B2; s[y] = A2; }
            }
            __syncthreads();
        }
    }

    // ---- b) gather: decode key, one LDG.128 per candidate; zero output
    {
        unsigned long long key = s[t];
        unsigned lowb = (unsigned)key;
        int idx = (int)(lowb >> 7);
        int cl  = (int)(lowb & 127u);
        unsigned k32 = (unsigned)(key >> 32);
        unsigned up  = ~k32;
        unsigned ub  = (up & 0x80000000u) ? (up & 0x7FFFFFFFu) : ~up;
        float mc = __uint_as_float(ub);   // masked conf, bit-exact

        float4 b4 = make_float4(0.f, 0.f, 0.f, 0.f);
        float tc = -1.0f;
        if (idx < NPRED) { b4 = g_box4[idx]; tc = mc; } else { cl = 0; }

        s_tc[t]    = tc;
        s_keep[t]  = (tc > 0.25f) ? 1 : 0;
        s_cls[t]   = cl;
        s_outb4[t] = b4;

        float off = __fmul_rn((float)cl, 7680.0f);
        float4 o;
        o.x = __fadd_rn(b4.x, off);
        o.y = __fadd_rn(b4.y, off);
        o.z = __fadd_rn(b4.z, off);
        o.w = __fadd_rn(b4.w, off);
        s_ob4[t]  = o;
        s_area[t] = __fmul_rn(__fsub_rn(o.z, o.x), __fsub_rn(o.w, o.y));
    }
    for (int i = t; i < out_size; i += 1024) out[i] = 0.0f;
    __syncthreads();

    // ---- c1) per-class counts + ballot cache (warp w owns c = w, w+32, w+64)
    for (int c = w; c < NCLS; c += 32) {
        int cntc = 0;
        #pragma unroll 4
        for (int k = 0; k < 32; ++k) {
            int p2 = k * 32 + lane;
            int m = (s_cls[p2] == c) && s_keep[p2];
            unsigned b = __ballot_sync(0xffffffffu, m);
            if (lane == 0) s_ball[c * 32 + k] = b;
            cntc += __popc(b);
        }
        if (lane == 0) s_cnt[c] = cntc;
    }
    __syncthreads();

    // ---- c2) exclusive prefix scan of 80 counts (warp 0)
    if (t < 32) {
        int v0 = s_cnt[t];
        int v1 = s_cnt[32 + t];
        int v2 = (t < 16) ? s_cnt[64 + t] : 0;
        int s0 = v0, s1 = v1, s2 = v2;
        #pragma unroll
        for (int o = 1; o < 32; o <<= 1) {
            int n0 = __shfl_up_sync(0xffffffffu, s0, o);
            int n1 = __shfl_up_sync(0xffffffffu, s1, o);
            int n2 = __shfl_up_sync(0xffffffffu, s2, o);
            if (t >= o) { s0 += n0; s1 += n1; s2 += n2; }
        }
        int tot0 = __shfl_sync(0xffffffffu, s0, 31);
        int tot1 = __shfl_sync(0xffffffffu, s1, 31);
        s_off[t] = s0 - v0;
        s_off[32 + t] = tot0 + s1 - v1;
        if (t < 16) s_off[64 + t] = tot0 + tot1 + s2 - v2;
    }
    __syncthreads();

    // ---- c3) fill class lists (cached ballots) + per-class greedy NMS
    for (int c = w; c < NCLS; c += 32) {
        int base = s_off[c];
        int run = base;
        #pragma unroll 4
        for (int k = 0; k < 32; ++k) {
            unsigned b = s_ball[c * 32 + k];
            if ((b >> lane) & 1u)
                s_list[run + __popc(b & ((1u << lane) - 1u))] = k * 32 + lane;
            run += __popc(b);
        }
        int n = run - base;
        __syncwarp();
        for (int i = 0; i < n; ++i) {
            int pi = s_list[base + i];
            int alive = s_keep[pi];      // broadcast smem read
            if (alive) {
                float4 bi = s_ob4[pi];
                float  ai = s_area[pi];
                for (int m2 = i + 1 + lane; m2 < n; m2 += 32) {
                    int pm = s_list[base + m2];
                    float4 bj = s_ob4[pm];
                    float lx = fmaxf(bi.x, bj.x);
                    float ly = fmaxf(bi.y, bj.y);
                    float rx = fminf(bi.z, bj.z);
                    float ry = fminf(bi.w, bj.w);
                    float ww = fmaxf(__fsub_rn(rx, lx), 0.0f);
                    float hh = fmaxf(__fsub_rn(ry, ly), 0.0f);
                    float inter = __fmul_rn(ww, hh);
                    float den = __fadd_rn(
                        __fsub_rn(__fadd_rn(ai, s_area[pm]), inter), 1e-7f);
                    if (__fdiv_rn(inter, den) > 0.45f) s_keep[pm] = 0;
                }
            }
            __syncwarp();
        }
    }
    __syncthreads();

    // ---- d) compaction + output (kept candidates already conf-sorted)
    int alivebit = s_keep[t];
    unsigned b2 = __ballot_sync(0xffffffffu, alivebit);
    if (lane == 0) ws[w] = __popc(b2);
    __syncthreads();
    if (t < 32) {
        int v = ws[t];
        int inc = v;
        #pragma unroll
        for (int o = 1; o < 32; o <<= 1) {
            int n = __shfl_up_sync(0xffffffffu, inc, o);
            if (t >= o) inc += n;
        }
        wx[t] = inc - v;  // exclusive
    }
    __syncthreads();
    int rank = wx[w] + __popc(b2 & ((1u << lane) - 1u));
    if (alivebit && rank < MAXDET) {
        float4 ob = s_outb4[t];
        float* row = out + rank * 6;
        row[0] = ob.x;
        row[1] = ob.y;
        row[2] = ob.z;
        row[3] = ob.w;
        row[4] = s_tc[t];
        row[5] = (float)s_cls[t];
    }
}

// ---------------- launcher -------------------------------------------------
extern "C" void kernel_launch(void* const* d_in, const int* in_sizes, int n_in,
                              void* d_out, int out_size) {
    const float* preds = (const float*)d_in[0];  // (32,84,8400); batch 0 only
    float* out = (float*)d_out;

    cudaFuncSetAttribute(k_all, cudaFuncAttributeMaxDynamicSharedMemorySize,
                         NSORT * (int)sizeof(unsigned long long));

    k_prepsort<<<16, 512>>>(preds);
    k_all<<<1, 1024, NSORT * sizeof(unsigned long long)>>>(out, out_size);
}

// round 15
// speedup vs baseline: 5.9989x; 1.0367x over previous
#include <cuda_runtime.h>

#define NPRED 8400
#define NCLS  80
#define NSORT 16384
#define MAXDET 300

typedef unsigned long long u64;

// ---------------- scratch (device globals; no allocation allowed) ----------
__device__ float4 g_box4[NPRED];
__device__ u64    g_skey[NSORT];   // 16 sorted chunks of 1024

__device__ __forceinline__ u64 mn64(u64 a, u64 b) { return a < b ? a : b; }
__device__ __forceinline__ u64 mx64(u64 a, u64 b) { return a > b ? a : b; }
__device__ __forceinline__ u64 shflx(u64 v, int st) {
    return __shfl_xor_sync(0xffffffffu, v, st);
}

// Merge a bitonic 64-seq (a at pos lane, b at pos 32+lane) into asc/desc
// order. Pure register/shfl — warp-synchronous and deterministic.
__device__ __forceinline__ void bmerge64(u64& a, u64& b, int lane, bool asc) {
    u64 lo = mn64(a, b), hi = mx64(a, b);
    a = asc ? lo : hi;
    b = asc ? hi : lo;
    #pragma unroll
    for (int st = 16; st >= 1; st >>= 1) {
        u64 oa = shflx(a, st);
        u64 ob = shflx(b, st);
        bool up = (lane & st) != 0;
        bool km = (up == asc);   // keep max at this lane
        a = km ? mx64(a, oa) : mn64(a, oa);
        b = km ? mx64(b, ob) : mn64(b, ob);
    }
}

// Full bitonic sort of 64 elements held in registers (a = pos lane,
// b = pos 32+lane), final direction asc64.
__device__ __forceinline__ void warpsort64(u64& a, u64& b, int lane, bool asc64) {
    // sizes 2..16: direction pattern identical for both registers
    #pragma unroll
    for (int size = 2; size <= 16; size <<= 1) {
        #pragma unroll
        for (int st = size >> 1; st >= 1; st >>= 1) {
            bool up = (lane & st) != 0;
            bool asc = ((lane & size) == 0);
            bool km = (up == asc);
            u64 oa = shflx(a, st); a = km ? mx64(a, oa) : mn64(a, oa);
            u64 ob = shflx(b, st); b = km ? mx64(b, ob) : mn64(b, ob);
        }
    }
    // size 32: positions 0..31 ascending, positions 32..63 descending
    #pragma unroll
    for (int st = 16; st >= 1; st >>= 1) {
        bool up = (lane & st) != 0;
        u64 oa = shflx(a, st); a = up ? mx64(a, oa) : mn64(a, oa);
        u64 ob = shflx(b, st); b = up ? mn64(b, ob) : mx64(b, ob);
    }
    // size 64: final merge
    bmerge64(a, b, lane, asc64);
}

// ---------------- kernel 1: fused prep + per-chunk bitonic sort ------------
// Key = (conf-key32 << 32) | (idx << 7) | cls.  idx-major low bits preserve
// the reference tie-break; masked conf is bit-exactly recoverable from key32.
__global__ __launch_bounds__(512) void k_prepsort(const float* __restrict__ p) {
    __shared__ u64 sk[1024];
    int c = blockIdx.x;
    int t = threadIdx.x;  // 0..511
    int w = t >> 5, lane = t & 31;  // 16 warps, each owns 64-block [64w,64w+64)

    #pragma unroll
    for (int e = 0; e < 2; ++e) {
        int local = t + e * 512;
        int a2 = c * 1024 + local;
        u64 key = 0xFFFFFFFFFFFFFFFFull;  // sentinel
        if (a2 < NPRED) {
            float cx = p[0 * NPRED + a2];
            float cy = p[1 * NPRED + a2];
            float ww = p[2 * NPRED + a2];
            float hh = p[3 * NPRED + a2];
            float hw = __fmul_rn(ww, 0.5f);
            float hh2 = __fmul_rn(hh, 0.5f);
            float4 b4;
            b4.x = __fsub_rn(cx, hw);
            b4.y = __fsub_rn(cy, hh2);
            b4.z = __fadd_rn(cx, hw);
            b4.w = __fadd_rn(cy, hh2);
            g_box4[a2] = b4;

            float m = p[4 * NPRED + a2];
            int cl = 0;
            #pragma unroll 16
            for (int cc = 1; cc < NCLS; ++cc) {
                float v = p[(4 + cc) * NPRED + a2];
                if (v > m) { m = v; cl = cc; }   // first-max tie-break
            }
            float mc = (m > 0.25f) ? m : -1.0f;
            unsigned u = __float_as_uint(mc);
            u = (u & 0x80000000u) ? ~u : (u | 0x80000000u);  // monotone asc
            unsigned k = ~u;                                  // desc conf
            key = ((u64)k << 32) | ((unsigned)a2 << 7) | (unsigned)cl;
        }
        sk[local] = key;
    }
    __syncthreads();

    // sizes 2..64 entirely in registers per warp
    {
        u64 a = sk[w * 64 + lane], b = sk[w * 64 + 32 + lane];
        warpsort64(a, b, lane, ((w * 64) & 64) == 0);
        sk[w * 64 + lane] = a;
        sk[w * 64 + 32 + lane] = b;
    }
    __syncthreads();

    // sizes 128..1024: smem CEs for strides >= 64, register tail for <= 32
    for (int size = 128; size <= 1024; size <<= 1) {
        for (int stride = size >> 1; stride >= 64; stride >>= 1) {
            int low = t & (stride - 1);
            int i = ((t ^ low) << 1) | low;
            int j = i + stride;
            u64 A = sk[i], B = sk[j];
            bool asc = ((i & size) == 0);
            if ((A > B) == asc) { sk[i] = B; sk[j] = A; }
            __syncthreads();
        }
        u64 a = sk[w * 64 + lane], b = sk[w * 64 + 32 + lane];
        bmerge64(a, b, lane, ((w * 64) & size) == 0);
        sk[w * 64 + lane] = a;
        sk[w * 64 + 32 + lane] = b;
        __syncthreads();
    }

    g_skey[c * 1024 + t]       = sk[t];
    g_skey[c * 1024 + t + 512] = sk[t + 512];
}

// ---------------- kernel 2: merge + gather + per-class NMS + output --------
__global__ __launch_bounds__(1024) void k_all(float* __restrict__ out, int out_size) {
    extern __shared__ unsigned char dyn[];
    u64*     s       = (u64*)dyn;                 // [0, 131072)
    float4*  s_ob4   = (float4*)(dyn + 8192);     // 1024 f4: offset boxes
    float*   s_area  = (float*)(dyn + 24576);     // 1024 f
    float4*  s_outb4 = (float4*)(dyn + 28672);    // 1024 f4: original boxes
    float*   s_tc    = (float*)(dyn + 45056);     // 1024 f
    int*     s_cls   = (int*)(dyn + 49152);       // 1024
    int*     s_keep  = (int*)(dyn + 53248);       // 1024
    int*     s_list  = (int*)(dyn + 57344);       // 1024
    int*     s_cnt   = (int*)(dyn + 61440);       // 80
    int*     s_off   = (int*)(dyn + 61760);       // 80
    unsigned* s_ball = (unsigned*)(dyn + 62080);  // 80*32 ballot cache
    __shared__ int ws[32], wx[32];

    int t = threadIdx.x;  // 0..1023
    int w = t >> 5, lane = t & 31;

    // ---- a) load keys + tournament min-merge (full barriers + reg tails)
    #pragma unroll
    for (int i = 0; i < NSORT / 1024; ++i) s[t + i * 1024] = g_skey[t + i * 1024];
    __syncthreads();

    #pragma unroll
    for (int L = 1; L <= 4; ++L) {
        int half   = 1024 << (L - 1);
        int npairs = 16 >> L;
        // min step: C[i] = min(A[i], B[1023-i]) keeps global top-1024 (bitonic)
        for (int q = t; q < npairs * 1024; q += 1024) {
            int pr = q >> 10, i = q & 1023;
            int A = pr * (half * 2);
            u64 a = s[A + i], b = s[A + half + 1023 - i];
            s[A + i] = mn64(a, b);
        }
        __syncthreads();
        // cleanup strides 512..64 in smem
        for (int stride = 512; stride >= 64; stride >>= 1) {
            int nce = npairs * 512;
            for (int q = t; q < nce; q += 1024) {
                int pr = q / 512, b2 = q % 512;
                int low = b2 & (stride - 1);
                int i = ((b2 ^ low) << 1) | low;
                int x = pr * (half * 2) + i;
                int y = x + stride;
                u64 A2 = s[x], B2 = s[y];
                if (A2 > B2) { s[x] = B2; s[y] = A2; }
            }
            __syncthreads();
        }
        // register tail: strides 32..1 on each 64-block (ascending)
        int nblk = npairs * 16;
        for (int q = w; q < nblk; q += 32) {
            int seg = q >> 4, k = q & 15;
            int base = seg * (half * 2) + k * 64;
            u64 a = s[base + lane], b = s[base + 32 + lane];
            bmerge64(a, b, lane, true);
            s[base + lane] = a;
            s[base + 32 + lane] = b;
        }
        __syncthreads();
    }

    // ---- b) gather: decode key, one LDG.128 per candidate; zero output
    {
        u64 key = s[t];
        unsigned lowb = (unsigned)key;
        int idx = (int)(lowb >> 7);
        int cl  = (int)(lowb & 127u);
        unsigned k32 = (unsigned)(key >> 32);
        unsigned up  = ~k32;
        unsigned ub  = (up & 0x80000000u) ? (up & 0x7FFFFFFFu) : ~up;
        float mc = __uint_as_float(ub);   // masked conf, bit-exact

        float4 b4 = make_float4(0.f, 0.f, 0.f, 0.f);
        float tc = -1.0f;
        if (idx < NPRED) { b4 = g_box4[idx]; tc = mc; } else { cl = 0; }

        s_tc[t]    = tc;
        s_keep[t]  = (tc > 0.25f) ? 1 : 0;
        s_cls[t]   = cl;
        s_outb4[t] = b4;

        float off = __fmul_rn((float)cl, 7680.0f);
        float4 o;
        o.x = __fadd_rn(b4.x, off);
        o.y = __fadd_rn(b4.y, off);
        o.z = __fadd_rn(b4.z, off);
        o.w = __fadd_rn(b4.w, off);
        s_ob4[t]  = o;
        s_area[t] = __fmul_rn(__fsub_rn(o.z, o.x), __fsub_rn(o.w, o.y));
    }
    for (int i = t; i < out_size; i += 1024) out[i] = 0.0f;
    __syncthreads();

    // ---- c1) per-class counts + ballot cache (warp w owns c = w, w+32, w+64)
    for (int c = w; c < NCLS; c += 32) {
        int cntc = 0;
        #pragma unroll 4
        for (int k = 0; k < 32; ++k) {
            int p2 = k * 32 + lane;
            int m = (s_cls[p2] == c) && s_keep[p2];
            unsigned b = __ballot_sync(0xffffffffu, m);
            if (lane == 0) s_ball[c * 32 + k] = b;
            cntc += __popc(b);
        }
        if (lane == 0) s_cnt[c] = cntc;
    }
    __syncthreads();

    // ---- c2) exclusive prefix scan of 80 counts (warp 0)
    if (t < 32) {
        int v0 = s_cnt[t];
        int v1 = s_cnt[32 + t];
        int v2 = (t < 16) ? s_cnt[64 + t] : 0;
        int s0 = v0, s1 = v1, s2 = v2;
        #pragma unroll
        for (int o = 1; o < 32; o <<= 1) {
            int n0 = __shfl_up_sync(0xffffffffu, s0, o);
            int n1 = __shfl_up_sync(0xffffffffu, s1, o);
            int n2 = __shfl_up_sync(0xffffffffu, s2, o);
            if (t >= o) { s0 += n0; s1 += n1; s2 += n2; }
        }
        int tot0 = __shfl_sync(0xffffffffu, s0, 31);
        int tot1 = __shfl_sync(0xffffffffu, s1, 31);
        s_off[t] = s0 - v0;
        s_off[32 + t] = tot0 + s1 - v1;
        if (t < 16) s_off[64 + t] = tot0 + tot1 + s2 - v2;
    }
    __syncthreads();

    // ---- c3) fill class lists (cached ballots) + per-class greedy NMS
    for (int c = w; c < NCLS; c += 32) {
        int base = s_off[c];
        int run = base;
        #pragma unroll 4
        for (int k = 0; k < 32; ++k) {
            unsigned b = s_ball[c * 32 + k];
            if ((b >> lane) & 1u)
                s_list[run + __popc(b & ((1u << lane) - 1u))] = k * 32 + lane;
            run += __popc(b);
        }
        int n = run - base;
        __syncwarp();
        for (int i = 0; i < n; ++i) {
            int pi = s_list[base + i];
            int alive = s_keep[pi];      // broadcast smem read
            if (alive) {
                float4 bi = s_ob4[pi];
                float  ai = s_area[pi];
                for (int m2 = i + 1 + lane; m2 < n; m2 += 32) {
                    int pm = s_list[base + m2];
                    float4 bj = s_ob4[pm];
                    float lx = fmaxf(bi.x, bj.x);
                    float ly = fmaxf(bi.y, bj.y);
                    float rx = fminf(bi.z, bj.z);
                    float ry = fminf(bi.w, bj.w);
                    float ww = fmaxf(__fsub_rn(rx, lx), 0.0f);
                    float hh = fmaxf(__fsub_rn(ry, ly), 0.0f);
                    float inter = __fmul_rn(ww, hh);
                    float den = __fadd_rn(
                        __fsub_rn(__fadd_rn(ai, s_area[pm]), inter), 1e-7f);
                    if (__fdiv_rn(inter, den) > 0.45f) s_keep[pm] = 0;
                }
            }
            __syncwarp();
        }
    }
    __syncthreads();

    // ---- d) compaction + output (kept candidates already conf-sorted)
    int alivebit = s_keep[t];
    unsigned b2 = __ballot_sync(0xffffffffu, alivebit);
    if (lane == 0) ws[w] = __popc(b2);
    __syncthreads();
    if (t < 32) {
        int v = ws[t];
        int inc = v;
        #pragma unroll
        for (int o = 1; o < 32; o <<= 1) {
            int n = __shfl_up_sync(0xffffffffu, inc, o);
            if (t >= o) inc += n;
        }
        wx[t] = inc - v;  // exclusive
    }
    __syncthreads();
    int rank = wx[w] + __popc(b2 & ((1u << lane) - 1u));
    if (alivebit && rank < MAXDET) {
        float4 ob = s_outb4[t];
        float* row = out + rank * 6;
        row[0] = ob.x;
        row[1] = ob.y;
        row[2] = ob.z;
        row[3] = ob.w;
        row[4] = s_tc[t];
        row[5] = (float)s_cls[t];
    }
}

// ---------------- launcher -------------------------------------------------
extern "C" void kernel_launch(void* const* d_in, const int* in_sizes, int n_in,
                              void* d_out, int out_size) {
    const float* preds = (const float*)d_in[0];  // (32,84,8400); batch 0 only
    float* out = (float*)d_out;

    cudaFuncSetAttribute(k_all, cudaFuncAttributeMaxDynamicSharedMemorySize,
                         NSORT * (int)sizeof(u64));

    k_prepsort<<<16, 512>>>(preds);
    k_all<<<1, 1024, NSORT * sizeof(u64)>>>(out, out_size);
}

// round 16
// speedup vs baseline: 7.3110x; 1.2187x over previous
#include <cuda_runtime.h>

#define NPRED 8400
#define NCLS  80
#define NLIST 8192
#define MAXDET 300

typedef unsigned long long u64;

// ---------------- scratch (device globals; no allocation allowed) ----------
__device__ float4 g_box4[NPRED];
__device__ u64    g_skey[NLIST];   // 8 sorted lists of 1024 (per-block top-1024)

__device__ __forceinline__ u64 mn64(u64 a, u64 b) { return a < b ? a : b; }
__device__ __forceinline__ u64 mx64(u64 a, u64 b) { return a > b ? a : b; }
__device__ __forceinline__ u64 shflx(u64 v, int st) {
    return __shfl_xor_sync(0xffffffffu, v, st);
}

// Merge a bitonic 64-seq (a at pos lane, b at pos 32+lane) into asc/desc
// order. Pure register/shfl — warp-synchronous and deterministic.
__device__ __forceinline__ void bmerge64(u64& a, u64& b, int lane, bool asc) {
    u64 lo = mn64(a, b), hi = mx64(a, b);
    a = asc ? lo : hi;
    b = asc ? hi : lo;
    #pragma unroll
    for (int st = 16; st >= 1; st >>= 1) {
        u64 oa = shflx(a, st);
        u64 ob = shflx(b, st);
        bool up = (lane & st) != 0;
        bool km = (up == asc);   // keep max at this lane
        a = km ? mx64(a, oa) : mn64(a, oa);
        b = km ? mx64(b, ob) : mn64(b, ob);
    }
}

// Full bitonic sort of 64 register-resident elements, final direction asc64.
__device__ __forceinline__ void warpsort64(u64& a, u64& b, int lane, bool asc64) {
    #pragma unroll
    for (int size = 2; size <= 16; size <<= 1) {
        #pragma unroll
        for (int st = size >> 1; st >= 1; st >>= 1) {
            bool up = (lane & st) != 0;
            bool asc = ((lane & size) == 0);
            bool km = (up == asc);
            u64 oa = shflx(a, st); a = km ? mx64(a, oa) : mn64(a, oa);
            u64 ob = shflx(b, st); b = km ? mx64(b, ob) : mn64(b, ob);
        }
    }
    #pragma unroll
    for (int st = 16; st >= 1; st >>= 1) {
        bool up = (lane & st) != 0;
        u64 oa = shflx(a, st); a = up ? mx64(a, oa) : mn64(a, oa);
        u64 ob = shflx(b, st); b = up ? mn64(b, ob) : mx64(b, ob);
    }
    bmerge64(a, b, lane, asc64);
}

// ---------------- kernel 1: prep + sort 2 chunks + local min-merge ---------
// 8 blocks x 1024 threads; block handles anchors [blk*2048, blk*2048+2048).
// Halves sorted concurrently in disjoint smem, then min-merged to the exact
// top-1024 of the 2048 (sorted ascending).  Key = (conf<<32)|(idx<<7)|cls.
__global__ __launch_bounds__(1024) void k_prepsort(const float* __restrict__ p) {
    __shared__ u64 sk[2048];
    int blk = blockIdx.x;           // 0..7
    int t = threadIdx.x;            // 0..1023
    int lane = t & 31;
    int th = t & 511;               // thread within half
    int wh = th >> 5;               // warp within half, 0..15
    int hb = (t >> 9) << 10;        // half base: 0 or 1024

    #pragma unroll
    for (int e = 0; e < 2; ++e) {
        int local = t + e * 1024;
        int a2 = blk * 2048 + local;
        u64 key = 0xFFFFFFFFFFFFFFFFull;  // sentinel
        if (a2 < NPRED) {
            float cx = p[0 * NPRED + a2];
            float cy = p[1 * NPRED + a2];
            float ww = p[2 * NPRED + a2];
            float hh = p[3 * NPRED + a2];
            float hw = __fmul_rn(ww, 0.5f);
            float hv = __fmul_rn(hh, 0.5f);
            float4 b4;
            b4.x = __fsub_rn(cx, hw);
            b4.y = __fsub_rn(cy, hv);
            b4.z = __fadd_rn(cx, hw);
            b4.w = __fadd_rn(cy, hv);
            g_box4[a2] = b4;

            float m = p[4 * NPRED + a2];
            int cl = 0;
            #pragma unroll 16
            for (int cc = 1; cc < NCLS; ++cc) {
                float v = p[(4 + cc) * NPRED + a2];
                if (v > m) { m = v; cl = cc; }   // first-max tie-break
            }
            float mc = (m > 0.25f) ? m : -1.0f;
            unsigned u = __float_as_uint(mc);
            u = (u & 0x80000000u) ? ~u : (u | 0x80000000u);  // monotone asc
            unsigned k = ~u;                                  // desc conf
            key = ((u64)k << 32) | ((unsigned)a2 << 7) | (unsigned)cl;
        }
        sk[local] = key;
    }
    __syncthreads();

    // --- sort each 1024-half ascending (both halves concurrently) ---
    {
        u64 a = sk[hb + wh * 64 + lane], b = sk[hb + wh * 64 + 32 + lane];
        warpsort64(a, b, lane, ((wh * 64) & 64) == 0);
        sk[hb + wh * 64 + lane] = a;
        sk[hb + wh * 64 + 32 + lane] = b;
    }
    __syncthreads();
    for (int size = 128; size <= 1024; size <<= 1) {
        for (int stride = size >> 1; stride >= 64; stride >>= 1) {
            int low = th & (stride - 1);
            int i = ((th ^ low) << 1) | low;
            int j = i + stride;
            u64 A = sk[hb + i], B = sk[hb + j];
            bool asc = ((i & size) == 0);
            if ((A > B) == asc) { sk[hb + i] = B; sk[hb + j] = A; }
            __syncthreads();
        }
        u64 a = sk[hb + wh * 64 + lane], b = sk[hb + wh * 64 + 32 + lane];
        bmerge64(a, b, lane, ((wh * 64) & size) == 0);
        sk[hb + wh * 64 + lane] = a;
        sk[hb + wh * 64 + 32 + lane] = b;
        __syncthreads();
    }

    // --- min-merge the halves: exact top-1024 of 2048 (bitonic result) ---
    sk[t] = mn64(sk[t], sk[2047 - t]);   // thread t owns slot t exclusively
    __syncthreads();
    for (int stride = 512; stride >= 64; stride >>= 1) {
        if (t < 512) {
            int low = t & (stride - 1);
            int i = ((t ^ low) << 1) | low;
            int j = i + stride;
            u64 A = sk[i], B = sk[j];
            if (A > B) { sk[i] = B; sk[j] = A; }
        }
        __syncthreads();
    }
    if ((t >> 5) < 16) {
        int wb = t >> 5;
        u64 a = sk[wb * 64 + lane], b = sk[wb * 64 + 32 + lane];
        bmerge64(a, b, lane, true);
        sk[wb * 64 + lane] = a;
        sk[wb * 64 + 32 + lane] = b;
    }
    __syncthreads();

    g_skey[blk * 1024 + t] = sk[t];
}

// ---------------- kernel 2: merge + gather + per-class NMS + output --------
__global__ __launch_bounds__(1024) void k_all(float* __restrict__ out, int out_size) {
    extern __shared__ unsigned char dyn[];
    u64*     s       = (u64*)dyn;                 // [0, 65536)
    float4*  s_ob4   = (float4*)(dyn + 8192);     // 1024 f4: offset boxes
    float*   s_area  = (float*)(dyn + 24576);     // 1024 f
    float4*  s_outb4 = (float4*)(dyn + 28672);    // 1024 f4: original boxes
    float*   s_tc    = (float*)(dyn + 45056);     // 1024 f
    int*     s_cls   = (int*)(dyn + 49152);       // 1024
    int*     s_keep  = (int*)(dyn + 53248);       // 1024
    int*     s_list  = (int*)(dyn + 57344);       // 1024
    int*     s_cnt   = (int*)(dyn + 61440);       // 80
    int*     s_off   = (int*)(dyn + 61760);       // 80
    int*     s_wcnt  = (int*)(dyn + 62080);       // 80*32 per-warp class counts
    __shared__ int ws[32], wx[32];

    int t = threadIdx.x;  // 0..1023
    int w = t >> 5, lane = t & 31;

    // ---- a) load 8 sorted lists + tournament min-merge (3 levels)
    #pragma unroll
    for (int i = 0; i < NLIST / 1024; ++i) s[t + i * 1024] = g_skey[t + i * 1024];
    __syncthreads();

    #pragma unroll
    for (int L = 1; L <= 3; ++L) {
        int half   = 1024 << (L - 1);
        int npairs = 8 >> L;
        for (int q = t; q < npairs * 1024; q += 1024) {
            int pr = q >> 10, i = q & 1023;
            int A = pr * (half * 2);
            s[A + i] = mn64(s[A + i], s[A + half + 1023 - i]);
        }
        __syncthreads();
        for (int stride = 512; stride >= 64; stride >>= 1) {
            int nce = npairs * 512;
            for (int q = t; q < nce; q += 1024) {
                int pr = q / 512, b2 = q % 512;
                int low = b2 & (stride - 1);
                int i = ((b2 ^ low) << 1) | low;
                int x = pr * (half * 2) + i;
                int y = x + stride;
                u64 A2 = s[x], B2 = s[y];
                if (A2 > B2) { s[x] = B2; s[y] = A2; }
            }
            __syncthreads();
        }
        int nblk = npairs * 16;
        for (int q = w; q < nblk; q += 32) {
            int seg = q >> 4, k = q & 15;
            int base = seg * (half * 2) + k * 64;
            u64 a = s[base + lane], b = s[base + 32 + lane];
            bmerge64(a, b, lane, true);
            s[base + lane] = a;
            s[base + 32 + lane] = b;
        }
        __syncthreads();
    }

    // ---- b) gather: decode key, one LDG.128 per candidate; zero scratch
    {
        u64 key = s[t];
        unsigned lowb = (unsigned)key;
        int idx = (int)(lowb >> 7);
        int cl  = (int)(lowb & 127u);
        unsigned k32 = (unsigned)(key >> 32);
        unsigned up  = ~k32;
        unsigned ub  = (up & 0x80000000u) ? (up & 0x7FFFFFFFu) : ~up;
        float mc = __uint_as_float(ub);   // masked conf, bit-exact

        float4 b4 = make_float4(0.f, 0.f, 0.f, 0.f);
        float tc = -1.0f;
        if (idx < NPRED) { b4 = g_box4[idx]; tc = mc; } else { cl = 0; }

        s_tc[t]    = tc;
        s_keep[t]  = (tc > 0.25f) ? 1 : 0;
        s_cls[t]   = cl;
        s_outb4[t] = b4;

        float off = __fmul_rn((float)cl, 7680.0f);
        float4 o;
        o.x = __fadd_rn(b4.x, off);
        o.y = __fadd_rn(b4.y, off);
        o.z = __fadd_rn(b4.z, off);
        o.w = __fadd_rn(b4.w, off);
        s_ob4[t]  = o;
        s_area[t] = __fmul_rn(__fsub_rn(o.z, o.x), __fsub_rn(o.w, o.y));
    }
    for (int i = t; i < NCLS * 32; i += 1024) s_wcnt[i] = 0;
    for (int i = t; i < out_size; i += 1024) out[i] = 0.0f;
    __syncthreads();

    // ---- c1) per-warp class counts + in-warp ranks via match_any
    int myc = s_keep[t] ? s_cls[t] : 127;   // 127 = dropped sentinel
    unsigned mm = __match_any_sync(0xffffffffu, myc);
    int rinw = __popc(mm & ((1u << lane) - 1u));
    if (rinw == 0 && myc < NCLS) s_wcnt[myc * 32 + w] = __popc(mm);
    __syncthreads();

    // ---- c2a) per-class prefix over the 32 warps (threads 0..79)
    if (t < NCLS) {
        int acc = 0;
        #pragma unroll 8
        for (int ww2 = 0; ww2 < 32; ++ww2) {
            int v = s_wcnt[t * 32 + ww2];
            s_wcnt[t * 32 + ww2] = acc;
            acc += v;
        }
        s_cnt[t] = acc;
    }
    __syncthreads();

    // ---- c2b) exclusive prefix scan of 80 class totals (warp 0)
    if (t < 32) {
        int v0 = s_cnt[t];
        int v1 = s_cnt[32 + t];
        int v2 = (t < 16) ? s_cnt[64 + t] : 0;
        int s0 = v0, s1 = v1, s2 = v2;
        #pragma unroll
        for (int o = 1; o < 32; o <<= 1) {
            int n0 = __shfl_up_sync(0xffffffffu, s0, o);
            int n1 = __shfl_up_sync(0xffffffffu, s1, o);
            int n2 = __shfl_up_sync(0xffffffffu, s2, o);
            if (t >= o) { s0 += n0; s1 += n1; s2 += n2; }
        }
        int tot0 = __shfl_sync(0xffffffffu, s0, 31);
        int tot1 = __shfl_sync(0xffffffffu, s1, 31);
        s_off[t] = s0 - v0;
        s_off[32 + t] = tot0 + s1 - v1;
        if (t < 16) s_off[64 + t] = tot0 + tot1 + s2 - v2;
    }
    __syncthreads();

    // ---- c2c) placement: list order = candidate index order (conf desc)
    if (myc < NCLS) s_list[s_off[myc] + s_wcnt[myc * 32 + w] + rinw] = t;
    __syncthreads();

    // ---- c3) per-class greedy NMS (warp w owns classes w, w+32, w+64)
    for (int c = w; c < NCLS; c += 32) {
        int base = s_off[c];
        int n = s_cnt[c];
        if (n == 0) continue;
        if (n <= 32) {
            // fast path: parallel suppressor masks + ballot chain
            int p2 = -1;
            float4 bj = make_float4(0.f, 0.f, 0.f, 0.f);
            float aj = 0.f;
            if (lane < n) { p2 = s_list[base + lane]; bj = s_ob4[p2]; aj = s_area[p2]; }
            unsigned m = 0;  // bit i set: candidate i (i<lane) suppresses me
            for (int i = 0; i < n - 1; ++i) {
                float bx = __shfl_sync(0xffffffffu, bj.x, i);
                float by = __shfl_sync(0xffffffffu, bj.y, i);
                float bz = __shfl_sync(0xffffffffu, bj.z, i);
                float bw = __shfl_sync(0xffffffffu, bj.w, i);
                float ba = __shfl_sync(0xffffffffu, aj, i);
                if (lane > i && lane < n) {
                    float lx = fmaxf(bx, bj.x);
                    float ly = fmaxf(by, bj.y);
                    float rx = fminf(bz, bj.z);
                    float ry = fminf(bw, bj.w);
                    float ww2 = fmaxf(__fsub_rn(rx, lx), 0.0f);
                    float hh2 = fmaxf(__fsub_rn(ry, ly), 0.0f);
                    float inter = __fmul_rn(ww2, hh2);
                    float den = __fadd_rn(
                        __fsub_rn(__fadd_rn(ba, aj), inter), 1e-7f);
                    if (__fdiv_rn(inter, den) > 0.45f) m |= (1u << i);
                }
            }
            unsigned rem = 0;  // suppressed set (uniform across lanes)
            for (int i = 0; i < n; ++i) {
                unsigned colb = __ballot_sync(0xffffffffu, (m >> i) & 1u);
                if (!((rem >> i) & 1u)) rem |= colb;
            }
            if (lane < n && ((rem >> lane) & 1u)) s_keep[p2] = 0;
        } else {
            // fallback: proven serial chain
            __syncwarp();
            for (int i = 0; i < n; ++i) {
                int pi = s_list[base + i];
                int alive = s_keep[pi];
                if (alive) {
                    float4 bi = s_ob4[pi];
                    float  ai = s_area[pi];
                    for (int m2 = i + 1 + lane; m2 < n; m2 += 32) {
                        int pm = s_list[base + m2];
                        float4 bj2 = s_ob4[pm];
                        float lx = fmaxf(bi.x, bj2.x);
                        float ly = fmaxf(bi.y, bj2.y);
                        float rx = fminf(bi.z, bj2.z);
                        float ry = fminf(bi.w, bj2.w);
                        float ww2 = fmaxf(__fsub_rn(rx, lx), 0.0f);
                        float hh2 = fmaxf(__fsub_rn(ry, ly), 0.0f);
                        float inter = __fmul_rn(ww2, hh2);
                        float den = __fadd_rn(
                            __fsub_rn(__fadd_rn(ai, s_area[pm]), inter), 1e-7f);
                        if (__fdiv_rn(inter, den) > 0.45f) s_keep[pm] = 0;
                    }
                }
                __syncwarp();
            }
        }
    }
    __syncthreads();

    // ---- d) compaction + output (kept candidates already conf-sorted)
    int alivebit = s_keep[t];
    unsigned b2 = __ballot_sync(0xffffffffu, alivebit);
    if (lane == 0) ws[w] = __popc(b2);
    __syncthreads();
    if (t < 32) {
        int v = ws[t];
        int inc = v;
        #pragma unroll
        for (int o = 1; o < 32; o <<= 1) {
            int n = __shfl_up_sync(0xffffffffu, inc, o);
            if (t >= o) inc += n;
        }
        wx[t] = inc - v;  // exclusive
    }
    __syncthreads();
    int rank = wx[w] + __popc(b2 & ((1u << lane) - 1u));
    if (alivebit && rank < MAXDET) {
        float4 ob = s_outb4[t];
        float* row = out + rank * 6;
        row[0] = ob.x;
        row[1] = ob.y;
        row[2] = ob.z;
        row[3] = ob.w;
        row[4] = s_tc[t];
        row[5] = (float)s_cls[t];
    }
}

// ---------------- launcher -------------------------------------------------
extern "C" void kernel_launch(void* const* d_in, const int* in_sizes, int n_in,
                              void* d_out, int out_size) {
    const float* preds = (const float*)d_in[0];  // (32,84,8400); batch 0 only
    float* out = (float*)d_out;

    cudaFuncSetAttribute(k_all, cudaFuncAttributeMaxDynamicSharedMemorySize, 73728);

    k_prepsort<<<8, 1024>>>(preds);
    k_all<<<1, 1024, 73728>>>(out, out_size);
}